// round 1
// baseline (speedup 1.0000x reference)
#include <cuda_runtime.h>

#define N_NODES 50000
#define N_EDGES 800000
#define DD 128
#define NEG 0.2f
#define NLAB 8
#define ET (N_EDGES + N_NODES)

// ---------------- device scratch (no allocs allowed) ----------------
__device__ __align__(16) float g_ox[N_NODES * DD];   // transformed features
__device__ float g_ai[N_NODES];                      // dst-side score
__device__ float g_aj[N_NODES];                      // src-side score
__device__ int   g_order[N_NODES];                   // nodes sorted by label group
__device__ int   g_counts[NLAB];
__device__ int   g_base[NLAB + 1];
__device__ int   g_lcur[NLAB];
__device__ int   g_deg[N_NODES];
__device__ int   g_off[N_NODES + 1];
__device__ int   g_cur[N_NODES];
__device__ int   g_csr[ET];                          // src per CSR slot (by dst)

// ---------------- init ----------------
__global__ void k_init() {
    int i = blockIdx.x * blockDim.x + threadIdx.x;
    if (i < NLAB) g_counts[i] = 0;
    if (i < N_NODES) g_deg[i] = 1;   // self loop pre-counted
}

// histogram labels (warp-aggregated) + in-degree count
__global__ void k_count(const int* __restrict__ ei, const int* __restrict__ label) {
    int i = blockIdx.x * blockDim.x + threadIdx.x;
    if (i < N_NODES) {
        int lb = label[i];
        if (lb < 1 || lb > 7) lb = 0;
        unsigned act = __activemask();
        unsigned peers = __match_any_sync(act, lb);
        int leader = __ffs(peers) - 1;
        if ((int)(threadIdx.x & 31) == leader)
            atomicAdd(&g_counts[lb], __popc(peers));
    }
    if (i < N_EDGES) {
        atomicAdd(&g_deg[ei[N_EDGES + i]], 1);  // dst
    }
}

__global__ void k_base() {
    int b = 0;
    for (int k = 0; k < NLAB; k++) { g_base[k] = b; g_lcur[k] = b; b += g_counts[k]; }
    g_base[NLAB] = b;
}

// scatter node ids into label-grouped order (warp-aggregated cursors)
__global__ void k_scatter(const int* __restrict__ label) {
    int i = blockIdx.x * blockDim.x + threadIdx.x;
    if (i >= N_NODES) return;
    int lb = label[i];
    if (lb < 1 || lb > 7) lb = 0;
    unsigned act = __activemask();
    unsigned peers = __match_any_sync(act, lb);
    int leader = __ffs(peers) - 1;
    int lane = threadIdx.x & 31;
    int rank = __popc(peers & ((1u << lane) - 1u));
    int basePos = 0;
    if (lane == leader) basePos = atomicAdd(&g_lcur[lb], __popc(peers));
    basePos = __shfl_sync(act, basePos, leader);
    g_order[basePos + rank] = i;
}

// single-block exclusive scan of g_deg -> g_off, g_cur
__global__ void k_scan() {
    __shared__ int ssum[1024];
    const int CH = (N_NODES + 1023) / 1024;  // 49
    int t = threadIdx.x;
    int b0 = t * CH;
    int s = 0;
    for (int i = 0; i < CH; i++) {
        int idx = b0 + i;
        if (idx < N_NODES) s += g_deg[idx];
    }
    ssum[t] = s;
    __syncthreads();
    for (int off = 1; off < 1024; off <<= 1) {
        int v = (t >= off) ? ssum[t - off] : 0;
        __syncthreads();
        ssum[t] += v;
        __syncthreads();
    }
    int run = (t == 0) ? 0 : ssum[t - 1];
    for (int i = 0; i < CH; i++) {
        int idx = b0 + i;
        if (idx < N_NODES) {
            g_off[idx] = run;
            g_cur[idx] = run;
            run += g_deg[idx];
        }
    }
    if (t == 1023) g_off[N_NODES] = ssum[1023];
}

// label-grouped tile GEMM: ox = x + W[k-1]^T x  (32 nodes x 128 out per block)
__global__ void __launch_bounds__(128) k_ox(const float* __restrict__ x,
                                            const float* __restrict__ W) {
    int k = blockIdx.y;
    int gbase = g_base[k];
    int start = gbase + blockIdx.x * 32;
    int end   = gbase + g_counts[k];
    if (start >= end) return;
    int nEff = min(32, end - start);

    __shared__ float xs[32 * DD];
    __shared__ int nid[32];
    int tid = threadIdx.x;
    if (tid < 32) nid[tid] = (tid < nEff) ? g_order[start + tid] : g_order[start];
    __syncthreads();

    // stage x rows (float4, coalesced)
    const float4* x4 = (const float4*)x;
    float4* xs4 = (float4*)xs;
    for (int idx = tid; idx < 32 * 32; idx += 128) {
        int j = idx >> 5, d4 = idx & 31;
        if (j < nEff) xs4[j * 32 + d4] = x4[nid[j] * 32 + d4];
    }
    __syncthreads();

    float4* ox4 = (float4*)g_ox;
    if (k == 0) {  // invalid label: ox = x
        for (int idx = tid; idx < 32 * 32; idx += 128) {
            int j = idx >> 5, d4 = idx & 31;
            if (j < nEff) ox4[nid[j] * 32 + d4] = xs4[j * 32 + d4];
        }
        return;
    }

    int o4 = tid & 31;   // output float4 index (channels 4*o4..4*o4+3)
    int jg = tid >> 5;   // node group: nodes {jg, jg+4, ..., jg+28}
    const float4* W4 = (const float4*)(W + (size_t)(k - 1) * DD * DD);

    float4 acc[8];
#pragma unroll
    for (int jj = 0; jj < 8; jj++) acc[jj] = make_float4(0.f, 0.f, 0.f, 0.f);

    for (int d = 0; d < DD; d++) {
        float4 w = W4[d * 32 + o4];
#pragma unroll
        for (int jj = 0; jj < 8; jj++) {
            float xv = xs[(jg + jj * 4) * DD + d];  // warp broadcast
            acc[jj].x += xv * w.x;
            acc[jj].y += xv * w.y;
            acc[jj].z += xv * w.z;
            acc[jj].w += xv * w.w;
        }
    }

#pragma unroll
    for (int jj = 0; jj < 8; jj++) {
        int j = jg + jj * 4;
        if (j < nEff) {
            float4 xv = xs4[j * 32 + o4];
            float4 r = make_float4(xv.x + acc[jj].x, xv.y + acc[jj].y,
                                   xv.z + acc[jj].z, xv.w + acc[jj].w);
            ox4[nid[j] * 32 + o4] = r;
        }
    }
}

// per-node attention scalars: ai = ox . att[0:128], aj = ox . att[128:256]
__global__ void k_aiaj(const float* __restrict__ att) {
    int w = (blockIdx.x * blockDim.x + threadIdx.x) >> 5;
    int lane = threadIdx.x & 31;
    if (w >= N_NODES) return;
    float4 v = ((const float4*)g_ox)[w * 32 + lane];
    float4 a = ((const float4*)att)[lane];
    float4 b = ((const float4*)att)[32 + lane];
    float si = v.x * a.x + v.y * a.y + v.z * a.z + v.w * a.w;
    float sj = v.x * b.x + v.y * b.y + v.z * b.z + v.w * b.w;
    for (int o = 16; o; o >>= 1) {
        si += __shfl_xor_sync(0xFFFFFFFFu, si, o);
        sj += __shfl_xor_sync(0xFFFFFFFFu, sj, o);
    }
    if (lane == 0) { g_ai[w] = si; g_aj[w] = sj; }
}

// CSR fill: edges + self loops
__global__ void k_fill(const int* __restrict__ ei) {
    int i = blockIdx.x * blockDim.x + threadIdx.x;
    if (i < N_EDGES) {
        int s = ei[i];
        int d = ei[N_EDGES + i];
        int pos = atomicAdd(&g_cur[d], 1);
        g_csr[pos] = s;
    } else if (i < ET) {
        int n = i - N_EDGES;
        int pos = atomicAdd(&g_cur[n], 1);
        g_csr[pos] = n;
    }
}

__device__ __forceinline__ float lrelu(float a) { return a > 0.f ? a : NEG * a; }

// warp per dst node: softmax over incoming edges + weighted gather of ox[src]
__global__ void __launch_bounds__(128) k_agg(float* __restrict__ out) {
    int node = (blockIdx.x * blockDim.x + threadIdx.x) >> 5;
    int lane = threadIdx.x & 31;
    if (node >= N_NODES) return;
    int beg = g_off[node], end2 = g_off[node + 1];
    float ain = g_ai[node];

    // pass 1: max (lane-parallel over edges)
    float m = -1e30f;
    for (int e = beg + lane; e < end2; e += 32)
        m = fmaxf(m, lrelu(ain + g_aj[g_csr[e]]));
    for (int o = 16; o; o >>= 1)
        m = fmaxf(m, __shfl_xor_sync(0xFFFFFFFFu, m, o));

    // pass 2: fused exp + denom + weighted float4 gather (4-edge unroll for MLP)
    const float4* ox4 = (const float4*)g_ox;
    float4 acc = make_float4(0.f, 0.f, 0.f, 0.f);
    float denom = 0.f;
    int e = beg;
    for (; e + 4 <= end2; e += 4) {
        int s0 = g_csr[e], s1 = g_csr[e + 1], s2 = g_csr[e + 2], s3 = g_csr[e + 3];
        float w0 = __expf(lrelu(ain + g_aj[s0]) - m);
        float w1 = __expf(lrelu(ain + g_aj[s1]) - m);
        float w2 = __expf(lrelu(ain + g_aj[s2]) - m);
        float w3 = __expf(lrelu(ain + g_aj[s3]) - m);
        float4 v0 = ox4[s0 * 32 + lane];
        float4 v1 = ox4[s1 * 32 + lane];
        float4 v2 = ox4[s2 * 32 + lane];
        float4 v3 = ox4[s3 * 32 + lane];
        denom += (w0 + w1) + (w2 + w3);
        acc.x += w0 * v0.x + w1 * v1.x + w2 * v2.x + w3 * v3.x;
        acc.y += w0 * v0.y + w1 * v1.y + w2 * v2.y + w3 * v3.y;
        acc.z += w0 * v0.z + w1 * v1.z + w2 * v2.z + w3 * v3.z;
        acc.w += w0 * v0.w + w1 * v1.w + w2 * v2.w + w3 * v3.w;
    }
    for (; e < end2; e++) {
        int s = g_csr[e];
        float w = __expf(lrelu(ain + g_aj[s]) - m);
        float4 v = ox4[s * 32 + lane];
        denom += w;
        acc.x += w * v.x; acc.y += w * v.y; acc.z += w * v.z; acc.w += w * v.w;
    }
    float inv = 1.f / (denom + 1e-16f);
    acc.x *= inv; acc.y *= inv; acc.z *= inv; acc.w *= inv;
    ((float4*)out)[node * 32 + lane] = acc;
}

// ---------------- launch ----------------
extern "C" void kernel_launch(void* const* d_in, const int* in_sizes, int n_in,
                              void* d_out, int out_size) {
    const float* x = nullptr;
    const int* ei = nullptr;
    const int* label = nullptr;
    const float* W = nullptr;
    const float* att = nullptr;
    for (int i = 0; i < n_in; i++) {
        switch (in_sizes[i]) {
            case N_NODES * DD:   x     = (const float*)d_in[i]; break;
            case 2 * N_EDGES:    ei    = (const int*)d_in[i];   break;
            case N_NODES:        label = (const int*)d_in[i];   break;
            case 7 * DD * DD:    W     = (const float*)d_in[i]; break;
            case 2 * DD:         att   = (const float*)d_in[i]; break;
            default: break;
        }
    }
    float* out = (float*)d_out;

    k_init<<<(N_NODES + 255) / 256, 256>>>();
    k_count<<<(N_EDGES + 255) / 256, 256>>>(ei, label);
    k_base<<<1, 1>>>();
    k_scatter<<<(N_NODES + 255) / 256, 256>>>(label);
    k_scan<<<1, 1024>>>();
    k_ox<<<dim3((N_NODES + 31) / 32, NLAB), 128>>>(x, W);
    k_aiaj<<<(N_NODES * 32 + 127) / 128, 128>>>(att);
    k_fill<<<(ET + 255) / 256, 256>>>(ei);
    k_agg<<<(N_NODES * 32 + 127) / 128, 128>>>(out);
}

// round 2
// speedup vs baseline: 1.1197x; 1.1197x over previous
#include <cuda_runtime.h>
#include <cuda_fp16.h>

#define N_NODES 50000
#define N_EDGES 800000
#define DD 128
#define NEG 0.2f
#define NLAB 8
#define ET (N_EDGES + N_NODES)

// ---------------- device scratch (no allocs allowed) ----------------
__device__ __align__(16) uint2 g_oxh[N_NODES * 32];  // fp16x4 packed transformed features
__device__ float g_ai[N_NODES];                      // dst-side score (fp32)
__device__ float g_aj[N_NODES];                      // src-side score (fp32)
__device__ int   g_order[N_NODES];                   // nodes grouped by label
__device__ int   g_counts[NLAB];
__device__ int   g_base[NLAB + 1];
__device__ int   g_lcur[NLAB];
__device__ int   g_deg[N_NODES];
__device__ int   g_off[N_NODES + 1];
__device__ int   g_cur[N_NODES];
__device__ int   g_csr[ET];                          // src per CSR slot (grouped by dst)

// ---------------- init ----------------
__global__ void k_init() {
    int i = blockIdx.x * blockDim.x + threadIdx.x;
    if (i < NLAB) g_counts[i] = 0;
    if (i < N_NODES) g_deg[i] = 1;   // self loop pre-counted
}

// label histogram (warp-aggregated) + in-degree count
__global__ void k_count(const int* __restrict__ ei, const int* __restrict__ label) {
    int i = blockIdx.x * blockDim.x + threadIdx.x;
    if (i < N_NODES) {
        int lb = label[i];
        if (lb < 1 || lb > 7) lb = 0;
        unsigned act = __activemask();
        unsigned peers = __match_any_sync(act, lb);
        int leader = __ffs(peers) - 1;
        if ((int)(threadIdx.x & 31) == leader)
            atomicAdd(&g_counts[lb], __popc(peers));
    }
    if (i < N_EDGES) {
        atomicAdd(&g_deg[ei[N_EDGES + i]], 1);  // dst
    }
}

// single block: label bases + exclusive scan of degrees
__global__ void k_scan() {
    __shared__ int ssum[1024];
    int t = threadIdx.x;
    if (t == 0) {
        int b = 0;
        for (int k = 0; k < NLAB; k++) { g_base[k] = b; g_lcur[k] = b; b += g_counts[k]; }
        g_base[NLAB] = b;
    }
    const int CH = (N_NODES + 1023) / 1024;  // 49
    int b0 = t * CH;
    int s = 0;
    for (int i = 0; i < CH; i++) {
        int idx = b0 + i;
        if (idx < N_NODES) s += g_deg[idx];
    }
    ssum[t] = s;
    __syncthreads();
    for (int off = 1; off < 1024; off <<= 1) {
        int v = (t >= off) ? ssum[t - off] : 0;
        __syncthreads();
        ssum[t] += v;
        __syncthreads();
    }
    int run = (t == 0) ? 0 : ssum[t - 1];
    for (int i = 0; i < CH; i++) {
        int idx = b0 + i;
        if (idx < N_NODES) {
            g_off[idx] = run;
            g_cur[idx] = run;
            run += g_deg[idx];
        }
    }
    if (t == 1023) g_off[N_NODES] = ssum[1023];
}

// fused: label-group scatter (i < N) + CSR fill (i < ET)
__global__ void k_build(const int* __restrict__ ei, const int* __restrict__ label) {
    int i = blockIdx.x * blockDim.x + threadIdx.x;
    if (i < N_NODES) {
        int lb = label[i];
        if (lb < 1 || lb > 7) lb = 0;
        unsigned act = __activemask();
        unsigned peers = __match_any_sync(act, lb);
        int leader = __ffs(peers) - 1;
        int lane = threadIdx.x & 31;
        int rank = __popc(peers & ((1u << lane) - 1u));
        int basePos = 0;
        if (lane == leader) basePos = atomicAdd(&g_lcur[lb], __popc(peers));
        basePos = __shfl_sync(act, basePos, leader);
        g_order[basePos + rank] = i;
    }
    if (i < N_EDGES) {
        int s = ei[i];
        int d = ei[N_EDGES + i];
        int pos = atomicAdd(&g_cur[d], 1);
        g_csr[pos] = s;
    } else if (i < ET) {
        int n = i - N_EDGES;
        int pos = atomicAdd(&g_cur[n], 1);
        g_csr[pos] = n;
    }
}

// label-grouped tile GEMM + fused epilogue:
//   r = x + W[k-1]^T x ;  g_oxh = half(r) ;  g_ai/g_aj = r.att dots
__global__ void __launch_bounds__(128) k_ox(const float* __restrict__ x,
                                            const float* __restrict__ W,
                                            const float* __restrict__ att) {
    int k = blockIdx.y;
    int gbase = g_base[k];
    int start = gbase + blockIdx.x * 32;
    int end   = gbase + g_counts[k];
    if (start >= end) return;
    int nEff = min(32, end - start);

    __shared__ float xs[32 * DD];
    __shared__ int nid[32];
    int tid = threadIdx.x;
    if (tid < 32) nid[tid] = (tid < nEff) ? g_order[start + tid] : g_order[start];
    __syncthreads();

    const float4* x4 = (const float4*)x;
    float4* xs4 = (float4*)xs;
    for (int idx = tid; idx < 32 * 32; idx += 128) {
        int j = idx >> 5, d4 = idx & 31;
        xs4[j * 32 + d4] = (j < nEff) ? x4[nid[j] * 32 + d4]
                                      : make_float4(0.f, 0.f, 0.f, 0.f);
    }
    __syncthreads();

    int o4 = tid & 31;   // output float4 index (channels 4*o4..4*o4+3)
    int jg = tid >> 5;   // warp jg owns nodes {jg, jg+4, ..., jg+28}

    float4 acc[8];
#pragma unroll
    for (int jj = 0; jj < 8; jj++) acc[jj] = make_float4(0.f, 0.f, 0.f, 0.f);

    if (k > 0) {
        const float4* W4 = (const float4*)(W + (size_t)(k - 1) * DD * DD);
        for (int d4 = 0; d4 < 32; d4++) {
            float4 w0 = W4[(d4 * 4 + 0) * 32 + o4];
            float4 w1 = W4[(d4 * 4 + 1) * 32 + o4];
            float4 w2 = W4[(d4 * 4 + 2) * 32 + o4];
            float4 w3 = W4[(d4 * 4 + 3) * 32 + o4];
#pragma unroll
            for (int jj = 0; jj < 8; jj++) {
                float4 xv = xs4[(jg + jj * 4) * 32 + d4];  // LDS.128 broadcast
                acc[jj].x += xv.x * w0.x + xv.y * w1.x + xv.z * w2.x + xv.w * w3.x;
                acc[jj].y += xv.x * w0.y + xv.y * w1.y + xv.z * w2.y + xv.w * w3.y;
                acc[jj].z += xv.x * w0.z + xv.y * w1.z + xv.z * w2.z + xv.w * w3.z;
                acc[jj].w += xv.x * w0.w + xv.y * w1.w + xv.z * w2.w + xv.w * w3.w;
            }
        }
    }

    float4 a4 = ((const float4*)att)[o4];
    float4 b4 = ((const float4*)att)[32 + o4];

#pragma unroll
    for (int jj = 0; jj < 8; jj++) {
        int j = jg + jj * 4;
        float4 xv = xs4[j * 32 + o4];
        float4 r = make_float4(xv.x + acc[jj].x, xv.y + acc[jj].y,
                               xv.z + acc[jj].z, xv.w + acc[jj].w);
        // attention dots (fp32, pre-rounding) — warp-reduce
        float si = r.x * a4.x + r.y * a4.y + r.z * a4.z + r.w * a4.w;
        float sj = r.x * b4.x + r.y * b4.y + r.z * b4.z + r.w * b4.w;
#pragma unroll
        for (int o = 16; o; o >>= 1) {
            si += __shfl_xor_sync(0xFFFFFFFFu, si, o);
            sj += __shfl_xor_sync(0xFFFFFFFFu, sj, o);
        }
        if (j < nEff) {
            int node = nid[j];
            __half2 h01 = __floats2half2_rn(r.x, r.y);
            __half2 h23 = __floats2half2_rn(r.z, r.w);
            uint2 pk;
            pk.x = *reinterpret_cast<unsigned*>(&h01);
            pk.y = *reinterpret_cast<unsigned*>(&h23);
            g_oxh[node * 32 + o4] = pk;
            if (o4 == 0) { g_ai[node] = si; g_aj[node] = sj; }
        }
    }
}

__device__ __forceinline__ float lrelu(float a) { return a > 0.f ? a : NEG * a; }

// warp per dst node: softmax over incoming edges + weighted fp16 gather
__global__ void __launch_bounds__(256) k_agg(float* __restrict__ out) {
    int node = (blockIdx.x * blockDim.x + threadIdx.x) >> 5;
    int lane = threadIdx.x & 31;
    if (node >= N_NODES) return;
    int beg = g_off[node], end2 = g_off[node + 1];
    float ain = g_ai[node];

    // pass 1: max
    float m = -1e30f;
    for (int e = beg + lane; e < end2; e += 32)
        m = fmaxf(m, lrelu(ain + g_aj[g_csr[e]]));
#pragma unroll
    for (int o = 16; o; o >>= 1)
        m = fmaxf(m, __shfl_xor_sync(0xFFFFFFFFu, m, o));

    // pass 2: fused exp + denom + weighted fp16 gather (4-edge unroll)
    float4 acc = make_float4(0.f, 0.f, 0.f, 0.f);
    float denom = 0.f;
    int e = beg;
    for (; e + 4 <= end2; e += 4) {
        int s0 = g_csr[e], s1 = g_csr[e + 1], s2 = g_csr[e + 2], s3 = g_csr[e + 3];
        float w0 = __expf(lrelu(ain + g_aj[s0]) - m);
        float w1 = __expf(lrelu(ain + g_aj[s1]) - m);
        float w2 = __expf(lrelu(ain + g_aj[s2]) - m);
        float w3 = __expf(lrelu(ain + g_aj[s3]) - m);
        uint2 p0 = g_oxh[s0 * 32 + lane];
        uint2 p1 = g_oxh[s1 * 32 + lane];
        uint2 p2 = g_oxh[s2 * 32 + lane];
        uint2 p3 = g_oxh[s3 * 32 + lane];
        denom += (w0 + w1) + (w2 + w3);
        float2 f01, f23;
        f01 = __half22float2(*reinterpret_cast<const __half2*>(&p0.x));
        f23 = __half22float2(*reinterpret_cast<const __half2*>(&p0.y));
        acc.x += w0 * f01.x; acc.y += w0 * f01.y; acc.z += w0 * f23.x; acc.w += w0 * f23.y;
        f01 = __half22float2(*reinterpret_cast<const __half2*>(&p1.x));
        f23 = __half22float2(*reinterpret_cast<const __half2*>(&p1.y));
        acc.x += w1 * f01.x; acc.y += w1 * f01.y; acc.z += w1 * f23.x; acc.w += w1 * f23.y;
        f01 = __half22float2(*reinterpret_cast<const __half2*>(&p2.x));
        f23 = __half22float2(*reinterpret_cast<const __half2*>(&p2.y));
        acc.x += w2 * f01.x; acc.y += w2 * f01.y; acc.z += w2 * f23.x; acc.w += w2 * f23.y;
        f01 = __half22float2(*reinterpret_cast<const __half2*>(&p3.x));
        f23 = __half22float2(*reinterpret_cast<const __half2*>(&p3.y));
        acc.x += w3 * f01.x; acc.y += w3 * f01.y; acc.z += w3 * f23.x; acc.w += w3 * f23.y;
    }
    for (; e < end2; e++) {
        int s = g_csr[e];
        float w = __expf(lrelu(ain + g_aj[s]) - m);
        uint2 p = g_oxh[s * 32 + lane];
        float2 f01 = __half22float2(*reinterpret_cast<const __half2*>(&p.x));
        float2 f23 = __half22float2(*reinterpret_cast<const __half2*>(&p.y));
        denom += w;
        acc.x += w * f01.x; acc.y += w * f01.y; acc.z += w * f23.x; acc.w += w * f23.y;
    }
    float inv = 1.f / (denom + 1e-16f);
    acc.x *= inv; acc.y *= inv; acc.z *= inv; acc.w *= inv;
    ((float4*)out)[node * 32 + lane] = acc;
}

// ---------------- launch ----------------
extern "C" void kernel_launch(void* const* d_in, const int* in_sizes, int n_in,
                              void* d_out, int out_size) {
    const float* x = nullptr;
    const int* ei = nullptr;
    const int* label = nullptr;
    const float* W = nullptr;
    const float* att = nullptr;
    for (int i = 0; i < n_in; i++) {
        switch (in_sizes[i]) {
            case N_NODES * DD:   x     = (const float*)d_in[i]; break;
            case 2 * N_EDGES:    ei    = (const int*)d_in[i];   break;
            case N_NODES:        label = (const int*)d_in[i];   break;
            case 7 * DD * DD:    W     = (const float*)d_in[i]; break;
            case 2 * DD:         att   = (const float*)d_in[i]; break;
            default: break;
        }
    }
    float* out = (float*)d_out;

    k_init <<<(N_NODES + 255) / 256, 256>>>();
    k_count<<<(N_EDGES + 255) / 256, 256>>>(ei, label);
    k_scan <<<1, 1024>>>();
    k_build<<<(ET + 255) / 256, 256>>>(ei, label);
    k_ox   <<<dim3((N_NODES + 31) / 32, NLAB), 128>>>(x, W, att);
    k_agg  <<<(N_NODES * 32 + 255) / 256, 256>>>(out);
}